// round 6
// baseline (speedup 1.0000x reference)
#include <cuda_runtime.h>
#include <cstdint>

#define B_  4
#define L_  2048
#define D_  512
#define DK_ 256

// Scratch (allocation-free per harness rules)
__device__ float g_Q[B_ * L_ * DK_];
__device__ float g_K[B_ * L_ * DK_];
__device__ float g_V[B_ * L_ * D_];
__device__ float g_QE[(size_t)B_ * L_ * L_];
__device__ float g_S[(size_t)B_ * L_ * L_];

__device__ __forceinline__ uint32_t cvt_tf32(float x) {
    uint32_t r;
    asm("cvt.rna.tf32.f32 %0, %1;" : "=r"(r) : "f"(x));
    return r;
}

__device__ __forceinline__ void mma_tf32(float c[4], const uint32_t a[4], const uint32_t b[2]) {
    asm volatile(
        "mma.sync.aligned.m16n8k8.row.col.f32.tf32.tf32.f32 "
        "{%0,%1,%2,%3},{%4,%5,%6,%7},{%8,%9},{%0,%1,%2,%3};"
        : "+f"(c[0]), "+f"(c[1]), "+f"(c[2]), "+f"(c[3])
        : "r"(a[0]), "r"(a[1]), "r"(a[2]), "r"(a[3]), "r"(b[0]), "r"(b[1]));
}

// ---------------------------------------------------------------------------
// TF32 tensor-core GEMM. Block tile 128x128, K-chunk 32, 256 threads = 8 warps
// (2x4 warp grid, warp tile 64x32). fp32 accumulate.
//
// K-side tiles (A always; B when TRANS_B) use an interleaved smem layout:
// within each 8-k group, word position 2c holds k=c and 2c+1 holds k=4+c
// (row stride 40 words). Fragment loads are single conflict-free LDS.64;
// global loads remain float4 (LDG.128); stores scatter 4x STS.32 (same
// wavefront count as STS.128).
//
//   TRANS_B=false: C = A[M,K] * B[K,N]           (row-major B)
//   TRANS_B=true : C = A[M,K] * B[N,K]^T
//   SKEW=true    : C = (A*B^T + skew(QE)) * 1/16 (QK^T epilogue)
// ---------------------------------------------------------------------------
template <bool TRANS_B, bool SKEW>
__global__ __launch_bounds__(256)
void tgemm(const float* __restrict__ A, const float* __restrict__ Bm,
           float* __restrict__ C, int M, int N, int Kd,
           long long sA, long long sB, long long sC,
           const float* __restrict__ QE)
{
    __shared__ uint32_t As[128 * 40];
    __shared__ uint32_t Bs[TRANS_B ? (128 * 40) : (32 * 136)];

    const int bz = blockIdx.z;
    A  += (size_t)bz * sA;
    Bm += (size_t)bz * sB;
    C  += (size_t)bz * sC;

    const int bm = blockIdx.y * 128;
    const int bn = blockIdx.x * 128;
    const int tid  = threadIdx.x;
    const int lane = tid & 31;
    const int warp = tid >> 5;
    const int wm = warp & 1;   // 0..1  (64-row slab)
    const int wn = warp >> 1;  // 0..3  (32-col slab)

    // K-side tile mapping: 32 rows x 4 row-blocks, 8 threads/row, float4 each
    const int arow  = tid >> 3;          // 0..31
    const int t7    = tid & 7;
    const int acol4 = t7 << 2;                      // global k offset (float4)
    const int abase = (t7 >> 1) * 8 + (t7 & 1);     // interleaved smem word base
    // NN B tile: 32x128 floats, [k][n] stride 136
    const int brow  = tid >> 5;          // 0..7
    const int bcol4 = (tid & 31) << 2;   // 0..124

    float acc[4][4][4];
#pragma unroll
    for (int i = 0; i < 4; i++)
#pragma unroll
        for (int j = 0; j < 4; j++)
#pragma unroll
            for (int e = 0; e < 4; e++) acc[i][j][e] = 0.f;

    float4 ra[4], rb[4];

    // ---- prologue global load (k0 = 0) ----
#pragma unroll
    for (int i = 0; i < 4; i++)
        ra[i] = *reinterpret_cast<const float4*>(
            A + (size_t)(bm + arow + 32 * i) * Kd + acol4);
#pragma unroll
    for (int i = 0; i < 4; i++) {
        if (TRANS_B)
            rb[i] = *reinterpret_cast<const float4*>(
                Bm + (size_t)(bn + arow + 32 * i) * Kd + acol4);
        else
            rb[i] = *reinterpret_cast<const float4*>(
                Bm + (size_t)(brow + 8 * i) * N + bn + bcol4);
    }

    for (int k0 = 0; k0 < Kd; k0 += 32) {
        // ---- store tiles (scatter into interleaved positions) ----
#pragma unroll
        for (int i = 0; i < 4; i++) {
            uint32_t* p = &As[(arow + 32 * i) * 40 + abase];
            p[0] = cvt_tf32(ra[i].x);
            p[2] = cvt_tf32(ra[i].y);
            p[4] = cvt_tf32(ra[i].z);
            p[6] = cvt_tf32(ra[i].w);
        }
#pragma unroll
        for (int i = 0; i < 4; i++) {
            if (TRANS_B) {
                uint32_t* p = &Bs[(arow + 32 * i) * 40 + abase];
                p[0] = cvt_tf32(rb[i].x);
                p[2] = cvt_tf32(rb[i].y);
                p[4] = cvt_tf32(rb[i].z);
                p[6] = cvt_tf32(rb[i].w);
            } else {
                *reinterpret_cast<uint4*>(&Bs[(brow + 8 * i) * 136 + bcol4]) =
                    make_uint4(cvt_tf32(rb[i].x), cvt_tf32(rb[i].y),
                               cvt_tf32(rb[i].z), cvt_tf32(rb[i].w));
            }
        }
        __syncthreads();

        // ---- prefetch next chunk into registers ----
        if (k0 + 32 < Kd) {
            const int kn = k0 + 32;
#pragma unroll
            for (int i = 0; i < 4; i++)
                ra[i] = *reinterpret_cast<const float4*>(
                    A + (size_t)(bm + arow + 32 * i) * Kd + kn + acol4);
#pragma unroll
            for (int i = 0; i < 4; i++) {
                if (TRANS_B)
                    rb[i] = *reinterpret_cast<const float4*>(
                        Bm + (size_t)(bn + arow + 32 * i) * Kd + kn + acol4);
                else
                    rb[i] = *reinterpret_cast<const float4*>(
                        Bm + (size_t)(kn + brow + 8 * i) * N + bn + bcol4);
            }
        }

        // ---- compute: 4 k8-steps ----
        const int fm  = wm * 64 + (lane >> 2);
        const int fc2 = 2 * (lane & 3);
#pragma unroll
        for (int kb = 0; kb < 4; kb++) {
            const int kw = kb * 8 + fc2;
            uint32_t af[4][4];
#pragma unroll
            for (int mi = 0; mi < 4; mi++) {
                uint2 lo = *reinterpret_cast<const uint2*>(&As[(fm + mi * 16) * 40 + kw]);
                uint2 hi = *reinterpret_cast<const uint2*>(&As[(fm + mi * 16 + 8) * 40 + kw]);
                af[mi][0] = lo.x; af[mi][1] = hi.x; af[mi][2] = lo.y; af[mi][3] = hi.y;
            }
            uint32_t bf[4][2];
#pragma unroll
            for (int ni = 0; ni < 4; ni++) {
                const int n = wn * 32 + ni * 8 + (lane >> 2);
                if (TRANS_B) {
                    uint2 bb = *reinterpret_cast<const uint2*>(&Bs[n * 40 + kw]);
                    bf[ni][0] = bb.x; bf[ni][1] = bb.y;
                } else {
                    bf[ni][0] = Bs[(kb * 8 + (lane & 3)) * 136 + n];
                    bf[ni][1] = Bs[(kb * 8 + 4 + (lane & 3)) * 136 + n];
                }
            }
#pragma unroll
            for (int mi = 0; mi < 4; mi++)
#pragma unroll
                for (int ni = 0; ni < 4; ni++)
                    mma_tf32(acc[mi][ni], af[mi], bf[ni]);
        }
        __syncthreads();
    }

    // ---- epilogue ----
    if (!SKEW) {
#pragma unroll
        for (int mi = 0; mi < 4; mi++) {
            const int r0 = bm + wm * 64 + mi * 16 + (lane >> 2);
#pragma unroll
            for (int ni = 0; ni < 4; ni++) {
                const int c0 = bn + wn * 32 + ni * 8 + 2 * (lane & 3);
                *reinterpret_cast<float2*>(C + (size_t)r0 * N + c0) =
                    make_float2(acc[mi][ni][0], acc[mi][ni][1]);
                *reinterpret_cast<float2*>(C + (size_t)(r0 + 8) * N + c0) =
                    make_float2(acc[mi][ni][2], acc[mi][ni][3]);
            }
        }
    } else {
        // Srel[l,m] = QE[l, m-l+L-1] (m<=l); 0 (m==l+1); QE[l+1, m-l-2] (m>=l+2)
        const float scale = 0.0625f;  // 1/sqrt(256)
        const int b = blockIdx.z;
#pragma unroll
        for (int mi = 0; mi < 4; mi++) {
            const int rbase = bm + wm * 64 + mi * 16 + (lane >> 2);
#pragma unroll
            for (int ni = 0; ni < 4; ni++) {
                const int c0 = bn + wn * 32 + ni * 8 + 2 * (lane & 3);
#pragma unroll
                for (int h = 0; h < 2; h++) {
                    const int l = rbase + 8 * h;
                    const size_t row0 = (size_t)(b * L_ + l) * L_;
                    const size_t row1 = (size_t)(b * L_ + l + 1) * L_;
                    float out[2];
#pragma unroll
                    for (int e = 0; e < 2; e++) {
                        const int m = c0 + e;
                        float srel;
                        if (m <= l)          srel = QE[row0 + (m - l + L_ - 1)];
                        else if (m == l + 1) srel = 0.f;
                        else                 srel = QE[row1 + (m - l - 2)];
                        out[e] = (acc[mi][ni][2 * h + e] + srel) * scale;
                    }
                    *reinterpret_cast<float2*>(C + (size_t)l * N + c0) =
                        make_float2(out[0], out[1]);
                }
            }
        }
    }
}

// ---------------------------------------------------------------------------
// Row softmax over 2048 elements: one block per row, 256 threads x 8 elements.
// ---------------------------------------------------------------------------
__global__ void softmax2048(float* __restrict__ S)
{
    __shared__ float red[8];
    const size_t row = blockIdx.x;
    float* p = S + row * (size_t)L_;
    const int tid = threadIdx.x;

    float v[8];
    float mx = -1e30f;
#pragma unroll
    for (int i = 0; i < 8; i++) {
        v[i] = p[tid + i * 256];
        mx = fmaxf(mx, v[i]);
    }
#pragma unroll
    for (int o = 16; o > 0; o >>= 1)
        mx = fmaxf(mx, __shfl_xor_sync(0xffffffffu, mx, o));
    if ((tid & 31) == 0) red[tid >> 5] = mx;
    __syncthreads();
    mx = red[0];
#pragma unroll
    for (int w = 1; w < 8; w++) mx = fmaxf(mx, red[w]);
    __syncthreads();

    float sum = 0.f;
#pragma unroll
    for (int i = 0; i < 8; i++) {
        v[i] = __expf(v[i] - mx);
        sum += v[i];
    }
#pragma unroll
    for (int o = 16; o > 0; o >>= 1)
        sum += __shfl_xor_sync(0xffffffffu, sum, o);
    if ((tid & 31) == 0) red[tid >> 5] = sum;
    __syncthreads();
    float tot = 0.f;
#pragma unroll
    for (int w = 0; w < 8; w++) tot += red[w];

    const float inv = 1.f / tot;
#pragma unroll
    for (int i = 0; i < 8; i++) p[tid + i * 256] = v[i] * inv;
}

// ---------------------------------------------------------------------------
extern "C" void kernel_launch(void* const* d_in, const int* in_sizes, int n_in,
                              void* d_out, int out_size)
{
    const float* inQ = (const float*)d_in[0];
    const float* inK = (const float*)d_in[1];
    const float* inV = (const float*)d_in[2];
    const float* Wq  = (const float*)d_in[3];
    const float* Wk  = (const float*)d_in[4];
    const float* Wv  = (const float*)d_in[5];
    const float* E   = (const float*)d_in[6];
    float* out = (float*)d_out;

    float *Q, *K, *V, *QE, *S;
    cudaGetSymbolAddress((void**)&Q,  g_Q);
    cudaGetSymbolAddress((void**)&K,  g_K);
    cudaGetSymbolAddress((void**)&V,  g_V);
    cudaGetSymbolAddress((void**)&QE, g_QE);
    cudaGetSymbolAddress((void**)&S,  g_S);

    const int BL = B_ * L_;  // 8192

    // Projections: [8192,512] x [512,{256,256,512}] (NN)
    tgemm<false, false><<<dim3(DK_ / 128, BL / 128, 1), 256>>>(
        inQ, Wq, Q, BL, DK_, D_, 0, 0, 0, nullptr);
    tgemm<false, false><<<dim3(DK_ / 128, BL / 128, 1), 256>>>(
        inK, Wk, K, BL, DK_, D_, 0, 0, 0, nullptr);
    tgemm<false, false><<<dim3(D_ / 128, BL / 128, 1), 256>>>(
        inV, Wv, V, BL, D_, D_, 0, 0, 0, nullptr);

    // QE = Q * E^T : [8192,256] x [2048,256]^T -> [8192,2048] (NT)
    tgemm<true, false><<<dim3(L_ / 128, BL / 128, 1), 256>>>(
        Q, E, QE, BL, L_, DK_, 0, 0, 0, nullptr);

    // S = (Q K^T + skew(QE)) / 16, batched over B (NT + skew epilogue)
    tgemm<true, true><<<dim3(L_ / 128, L_ / 128, B_), 256>>>(
        Q, K, S, L_, L_, DK_,
        (long long)L_ * DK_, (long long)L_ * DK_, (long long)L_ * L_, QE);

    // softmax along rows
    softmax2048<<<BL, 256>>>(S);

    // out = P * V, batched over B: [2048,2048] x [2048,512] (NN)
    tgemm<false, false><<<dim3(D_ / 128, L_ / 128, B_), 256>>>(
        S, V, out, L_, D_, L_,
        (long long)L_ * L_, (long long)L_ * D_, (long long)L_ * D_, nullptr);
}

// round 7
// speedup vs baseline: 1.0232x; 1.0232x over previous
#include <cuda_runtime.h>
#include <cstdint>

#define B_  4
#define L_  2048
#define D_  512
#define DK_ 256

// Scratch (allocation-free). Q/K/V/E hold TF32 bit patterns after producers run.
__device__ float g_Q[B_ * L_ * DK_];
__device__ float g_K[B_ * L_ * DK_];
__device__ float g_V[B_ * L_ * D_];
__device__ float g_E[L_ * DK_];
__device__ float g_QE[(size_t)B_ * L_ * L_];
__device__ float g_S[(size_t)B_ * L_ * L_];

__device__ __forceinline__ uint32_t cvt_tf32(float x) {
    uint32_t r;
    asm("cvt.rna.tf32.f32 %0, %1;" : "=r"(r) : "f"(x));
    return r;
}

__device__ __forceinline__ void mma_tf32(float c[4], const uint32_t a[4], const uint32_t b[2]) {
    asm volatile(
        "mma.sync.aligned.m16n8k8.row.col.f32.tf32.tf32.f32 "
        "{%0,%1,%2,%3},{%4,%5,%6,%7},{%8,%9},{%0,%1,%2,%3};"
        : "+f"(c[0]), "+f"(c[1]), "+f"(c[2]), "+f"(c[3])
        : "r"(a[0]), "r"(a[1]), "r"(a[2]), "r"(a[3]), "r"(b[0]), "r"(b[1]));
}

__device__ __forceinline__ void cp_async16(uint32_t smem_addr, const void* gptr) {
    asm volatile("cp.async.ca.shared.global [%0], [%1], 16;"
                 :: "r"(smem_addr), "l"(gptr));
}

// ---------------------------------------------------------------------------
// Projection GEMM (fp32 in, TF32-bit out). R3-proven path: block 128x128,
// K-chunk 32, register prefetch, cvt on smem store. Epilogue stores TF32 bits.
// C = A[M,K] * B[K,N], row-major.
// ---------------------------------------------------------------------------
__global__ __launch_bounds__(256)
void proj_gemm(const float* __restrict__ A, const float* __restrict__ Bm,
               uint32_t* __restrict__ C, int M, int N, int Kd)
{
    __shared__ uint32_t As[128 * 36];
    __shared__ uint32_t Bs[32 * 136];

    const int bm = blockIdx.y * 128;
    const int bn = blockIdx.x * 128;
    const int tid  = threadIdx.x;
    const int lane = tid & 31;
    const int warp = tid >> 5;
    const int wm = warp & 1;
    const int wn = warp >> 1;

    const int arow  = tid >> 3;
    const int acol4 = (tid & 7) << 2;
    const int brow  = tid >> 5;
    const int bcol4 = (tid & 31) << 2;

    float acc[4][4][4];
#pragma unroll
    for (int i = 0; i < 4; i++)
#pragma unroll
        for (int j = 0; j < 4; j++)
#pragma unroll
            for (int e = 0; e < 4; e++) acc[i][j][e] = 0.f;

    float4 ra[4], rb[4];
#pragma unroll
    for (int i = 0; i < 4; i++)
        ra[i] = *reinterpret_cast<const float4*>(
            A + (size_t)(bm + arow + 32 * i) * Kd + acol4);
#pragma unroll
    for (int i = 0; i < 4; i++)
        rb[i] = *reinterpret_cast<const float4*>(
            Bm + (size_t)(brow + 8 * i) * N + bn + bcol4);

    for (int k0 = 0; k0 < Kd; k0 += 32) {
#pragma unroll
        for (int i = 0; i < 4; i++)
            *reinterpret_cast<uint4*>(&As[(arow + 32 * i) * 36 + acol4]) =
                make_uint4(cvt_tf32(ra[i].x), cvt_tf32(ra[i].y),
                           cvt_tf32(ra[i].z), cvt_tf32(ra[i].w));
#pragma unroll
        for (int i = 0; i < 4; i++)
            *reinterpret_cast<uint4*>(&Bs[(brow + 8 * i) * 136 + bcol4]) =
                make_uint4(cvt_tf32(rb[i].x), cvt_tf32(rb[i].y),
                           cvt_tf32(rb[i].z), cvt_tf32(rb[i].w));
        __syncthreads();

        if (k0 + 32 < Kd) {
            const int kn = k0 + 32;
#pragma unroll
            for (int i = 0; i < 4; i++)
                ra[i] = *reinterpret_cast<const float4*>(
                    A + (size_t)(bm + arow + 32 * i) * Kd + kn + acol4);
#pragma unroll
            for (int i = 0; i < 4; i++)
                rb[i] = *reinterpret_cast<const float4*>(
                    Bm + (size_t)(kn + brow + 8 * i) * N + bn + bcol4);
        }

#pragma unroll
        for (int kb = 0; kb < 4; kb++) {
            const int kk = kb * 8;
            uint32_t af[4][4];
#pragma unroll
            for (int mi = 0; mi < 4; mi++) {
                const int m = wm * 64 + mi * 16 + (lane >> 2);
                const int kc = kk + (lane & 3);
                af[mi][0] = As[m * 36 + kc];
                af[mi][1] = As[(m + 8) * 36 + kc];
                af[mi][2] = As[m * 36 + kc + 4];
                af[mi][3] = As[(m + 8) * 36 + kc + 4];
            }
            uint32_t bf[4][2];
#pragma unroll
            for (int ni = 0; ni < 4; ni++) {
                const int n = wn * 32 + ni * 8 + (lane >> 2);
                bf[ni][0] = Bs[(kk + (lane & 3)) * 136 + n];
                bf[ni][1] = Bs[(kk + 4 + (lane & 3)) * 136 + n];
            }
#pragma unroll
            for (int mi = 0; mi < 4; mi++)
#pragma unroll
                for (int ni = 0; ni < 4; ni++)
                    mma_tf32(acc[mi][ni], af[mi], bf[ni]);
        }
        __syncthreads();
    }

#pragma unroll
    for (int mi = 0; mi < 4; mi++) {
        const int r0 = bm + wm * 64 + mi * 16 + (lane >> 2);
#pragma unroll
        for (int ni = 0; ni < 4; ni++) {
            const int c0 = bn + wn * 32 + ni * 8 + 2 * (lane & 3);
            *reinterpret_cast<uint2*>(C + (size_t)r0 * N + c0) =
                make_uint2(cvt_tf32(acc[mi][ni][0]), cvt_tf32(acc[mi][ni][1]));
            *reinterpret_cast<uint2*>(C + (size_t)(r0 + 8) * N + c0) =
                make_uint2(cvt_tf32(acc[mi][ni][2]), cvt_tf32(acc[mi][ni][3]));
        }
    }
}

// ---------------------------------------------------------------------------
// Async TF32 GEMM: operands are pre-converted TF32 bits in gmem. cp.async
// 2-stage pipeline, no register staging, no cvt. R3 fragment layout.
//   TRANS_B=false: C = A * B        (B row-major [K,N])
//   TRANS_B=true : C = A * B^T      (B row-major [N,K])
//   SKEW=true    : C = (A*B^T + skew(QE)) / 16
// ---------------------------------------------------------------------------
template <bool TRANS_B, bool SKEW>
__global__ __launch_bounds__(256)
void agemm(const uint32_t* __restrict__ A, const uint32_t* __restrict__ Bm,
           float* __restrict__ C, int M, int N, int Kd,
           long long sA, long long sB, long long sC,
           const float* __restrict__ QE)
{
    constexpr int ASZ = 128 * 36;
    constexpr int BSZ = TRANS_B ? (128 * 36) : (32 * 136);
    extern __shared__ uint32_t smem[];
    uint32_t* const Asm = smem;            // [2][ASZ]
    uint32_t* const Bsm = smem + 2 * ASZ;  // [2][BSZ]
    const uint32_t sA0 = (uint32_t)__cvta_generic_to_shared(Asm);
    const uint32_t sB0 = (uint32_t)__cvta_generic_to_shared(Bsm);

    const int bz = blockIdx.z;
    A  += (size_t)bz * sA;
    Bm += (size_t)bz * sB;
    C  += (size_t)bz * sC;

    const int bm = blockIdx.y * 128;
    const int bn = blockIdx.x * 128;
    const int tid  = threadIdx.x;
    const int lane = tid & 31;
    const int warp = tid >> 5;
    const int wm = warp & 1;
    const int wn = warp >> 1;

    const int arow  = tid >> 3;
    const int acol4 = (tid & 7) << 2;
    const int brow  = tid >> 5;
    const int bcol4 = (tid & 31) << 2;

    float acc[4][4][4];
#pragma unroll
    for (int i = 0; i < 4; i++)
#pragma unroll
        for (int j = 0; j < 4; j++)
#pragma unroll
            for (int e = 0; e < 4; e++) acc[i][j][e] = 0.f;

    // issue one 32-k chunk into stage st
    auto issue = [&](int k0, int st) {
        const uint32_t sa = sA0 + (uint32_t)st * ASZ * 4;
        const uint32_t sb = sB0 + (uint32_t)st * BSZ * 4;
#pragma unroll
        for (int i = 0; i < 4; i++)
            cp_async16(sa + ((arow + 32 * i) * 36 + acol4) * 4,
                       A + (size_t)(bm + arow + 32 * i) * Kd + k0 + acol4);
#pragma unroll
        for (int i = 0; i < 4; i++) {
            if (TRANS_B)
                cp_async16(sb + ((arow + 32 * i) * 36 + acol4) * 4,
                           Bm + (size_t)(bn + arow + 32 * i) * Kd + k0 + acol4);
            else
                cp_async16(sb + ((brow + 8 * i) * 136 + bcol4) * 4,
                           Bm + (size_t)(k0 + brow + 8 * i) * N + bn + bcol4);
        }
        asm volatile("cp.async.commit_group;");
    };

    const int C_CHUNKS = Kd >> 5;
    issue(0, 0);

    for (int c = 0; c < C_CHUNKS; c++) {
        if (c + 1 < C_CHUNKS) {
            issue((c + 1) << 5, (c + 1) & 1);
            asm volatile("cp.async.wait_group 1;");
        } else {
            asm volatile("cp.async.wait_group 0;");
        }
        __syncthreads();

        const uint32_t* As = Asm + (c & 1) * ASZ;
        const uint32_t* Bs = Bsm + (c & 1) * BSZ;

#pragma unroll
        for (int kb = 0; kb < 4; kb++) {
            const int kk = kb * 8;
            uint32_t af[4][4];
#pragma unroll
            for (int mi = 0; mi < 4; mi++) {
                const int m = wm * 64 + mi * 16 + (lane >> 2);
                const int kc = kk + (lane & 3);
                af[mi][0] = As[m * 36 + kc];
                af[mi][1] = As[(m + 8) * 36 + kc];
                af[mi][2] = As[m * 36 + kc + 4];
                af[mi][3] = As[(m + 8) * 36 + kc + 4];
            }
            uint32_t bf[4][2];
#pragma unroll
            for (int ni = 0; ni < 4; ni++) {
                const int n = wn * 32 + ni * 8 + (lane >> 2);
                if (TRANS_B) {
                    bf[ni][0] = Bs[n * 36 + kk + (lane & 3)];
                    bf[ni][1] = Bs[n * 36 + kk + 4 + (lane & 3)];
                } else {
                    bf[ni][0] = Bs[(kk + (lane & 3)) * 136 + n];
                    bf[ni][1] = Bs[(kk + 4 + (lane & 3)) * 136 + n];
                }
            }
#pragma unroll
            for (int mi = 0; mi < 4; mi++)
#pragma unroll
                for (int ni = 0; ni < 4; ni++)
                    mma_tf32(acc[mi][ni], af[mi], bf[ni]);
        }
        __syncthreads();
    }

    if (!SKEW) {
#pragma unroll
        for (int mi = 0; mi < 4; mi++) {
            const int r0 = bm + wm * 64 + mi * 16 + (lane >> 2);
#pragma unroll
            for (int ni = 0; ni < 4; ni++) {
                const int c0 = bn + wn * 32 + ni * 8 + 2 * (lane & 3);
                *reinterpret_cast<float2*>(C + (size_t)r0 * N + c0) =
                    make_float2(acc[mi][ni][0], acc[mi][ni][1]);
                *reinterpret_cast<float2*>(C + (size_t)(r0 + 8) * N + c0) =
                    make_float2(acc[mi][ni][2], acc[mi][ni][3]);
            }
        }
    } else {
        // Srel[l,m] = QE[l, m-l+L-1] (m<=l); 0 (m==l+1); QE[l+1, m-l-2] (m>=l+2)
        const float scale = 0.0625f;  // 1/sqrt(256)
        const int b = blockIdx.z;
#pragma unroll
        for (int mi = 0; mi < 4; mi++) {
            const int rbase = bm + wm * 64 + mi * 16 + (lane >> 2);
#pragma unroll
            for (int ni = 0; ni < 4; ni++) {
                const int c0 = bn + wn * 32 + ni * 8 + 2 * (lane & 3);
#pragma unroll
                for (int h = 0; h < 2; h++) {
                    const int l = rbase + 8 * h;
                    const size_t row0 = (size_t)(b * L_ + l) * L_;
                    const size_t row1 = (size_t)(b * L_ + l + 1) * L_;
                    float out[2];
#pragma unroll
                    for (int e = 0; e < 2; e++) {
                        const int m = c0 + e;
                        float srel;
                        if (m <= l)          srel = QE[row0 + (m - l + L_ - 1)];
                        else if (m == l + 1) srel = 0.f;
                        else                 srel = QE[row1 + (m - l - 2)];
                        out[e] = (acc[mi][ni][2 * h + e] + srel) * scale;
                    }
                    *reinterpret_cast<float2*>(C + (size_t)l * N + c0) =
                        make_float2(out[0], out[1]);
                }
            }
        }
    }
}

// ---------------------------------------------------------------------------
// Elementwise fp32 -> TF32-bit convert (for E).
// ---------------------------------------------------------------------------
__global__ void conv_tf32(const float* __restrict__ in, uint32_t* __restrict__ out, int n4)
{
    const int i = blockIdx.x * blockDim.x + threadIdx.x;
    if (i < n4) {
        float4 v = reinterpret_cast<const float4*>(in)[i];
        reinterpret_cast<uint4*>(out)[i] =
            make_uint4(cvt_tf32(v.x), cvt_tf32(v.y), cvt_tf32(v.z), cvt_tf32(v.w));
    }
}

// ---------------------------------------------------------------------------
// Row softmax over 2048 elements; writes TF32 bit patterns (consumed by agemm).
// ---------------------------------------------------------------------------
__global__ void softmax2048(float* __restrict__ S)
{
    __shared__ float red[8];
    const size_t row = blockIdx.x;
    float* p = S + row * (size_t)L_;
    const int tid = threadIdx.x;

    float v[8];
    float mx = -1e30f;
#pragma unroll
    for (int i = 0; i < 8; i++) {
        v[i] = p[tid + i * 256];
        mx = fmaxf(mx, v[i]);
    }
#pragma unroll
    for (int o = 16; o > 0; o >>= 1)
        mx = fmaxf(mx, __shfl_xor_sync(0xffffffffu, mx, o));
    if ((tid & 31) == 0) red[tid >> 5] = mx;
    __syncthreads();
    mx = red[0];
#pragma unroll
    for (int w = 1; w < 8; w++) mx = fmaxf(mx, red[w]);
    __syncthreads();

    float sum = 0.f;
#pragma unroll
    for (int i = 0; i < 8; i++) {
        v[i] = __expf(v[i] - mx);
        sum += v[i];
    }
#pragma unroll
    for (int o = 16; o > 0; o >>= 1)
        sum += __shfl_xor_sync(0xffffffffu, sum, o);
    if ((tid & 31) == 0) red[tid >> 5] = sum;
    __syncthreads();
    float tot = 0.f;
#pragma unroll
    for (int w = 0; w < 8; w++) tot += red[w];

    const float inv = 1.f / tot;
    uint32_t* pu = reinterpret_cast<uint32_t*>(p);
#pragma unroll
    for (int i = 0; i < 8; i++) pu[tid + i * 256] = cvt_tf32(v[i] * inv);
}

// ---------------------------------------------------------------------------
extern "C" void kernel_launch(void* const* d_in, const int* in_sizes, int n_in,
                              void* d_out, int out_size)
{
    const float* inQ = (const float*)d_in[0];
    const float* inK = (const float*)d_in[1];
    const float* inV = (const float*)d_in[2];
    const float* Wq  = (const float*)d_in[3];
    const float* Wk  = (const float*)d_in[4];
    const float* Wv  = (const float*)d_in[5];
    const float* E   = (const float*)d_in[6];
    float* out = (float*)d_out;

    float *Q, *K, *V, *Ec, *QE, *S;
    cudaGetSymbolAddress((void**)&Q,  g_Q);
    cudaGetSymbolAddress((void**)&K,  g_K);
    cudaGetSymbolAddress((void**)&V,  g_V);
    cudaGetSymbolAddress((void**)&Ec, g_E);
    cudaGetSymbolAddress((void**)&QE, g_QE);
    cudaGetSymbolAddress((void**)&S,  g_S);

    const int BL = B_ * L_;  // 8192

    // dynamic smem sizes for agemm variants
    const int SM_NT = 2 * (128 * 36 + 128 * 36) * 4;  // 73728
    const int SM_NN = 2 * (128 * 36 + 32 * 136) * 4;  // 71680
    cudaFuncSetAttribute(agemm<true,  false>, cudaFuncAttributeMaxDynamicSharedMemorySize, SM_NT);
    cudaFuncSetAttribute(agemm<true,  true >, cudaFuncAttributeMaxDynamicSharedMemorySize, SM_NT);
    cudaFuncSetAttribute(agemm<false, false>, cudaFuncAttributeMaxDynamicSharedMemorySize, SM_NN);

    // Projections: fp32 in -> TF32 bits out
    proj_gemm<<<dim3(DK_ / 128, BL / 128, 1), 256>>>(inQ, Wq, (uint32_t*)Q, BL, DK_, D_);
    proj_gemm<<<dim3(DK_ / 128, BL / 128, 1), 256>>>(inK, Wk, (uint32_t*)K, BL, DK_, D_);
    proj_gemm<<<dim3(D_  / 128, BL / 128, 1), 256>>>(inV, Wv, (uint32_t*)V, BL, D_,  D_);

    // E -> TF32 bits
    conv_tf32<<<(L_ * DK_ / 4 + 255) / 256, 256>>>(E, (uint32_t*)Ec, L_ * DK_ / 4);

    // QE = Q * E^T (NT)
    agemm<true, false><<<dim3(L_ / 128, BL / 128, 1), 256, SM_NT>>>(
        (const uint32_t*)Q, (const uint32_t*)Ec, QE, BL, L_, DK_, 0, 0, 0, nullptr);

    // S = (Q K^T + skew(QE)) / 16, batched (NT + skew epilogue)
    agemm<true, true><<<dim3(L_ / 128, L_ / 128, B_), 256, SM_NT>>>(
        (const uint32_t*)Q, (const uint32_t*)K, S, L_, L_, DK_,
        (long long)L_ * DK_, (long long)L_ * DK_, (long long)L_ * L_, QE);

    // softmax (writes TF32 bits)
    softmax2048<<<BL, 256>>>(S);

    // out = P * V, batched (NN)
    agemm<false, false><<<dim3(D_ / 128, L_ / 128, B_), 256, SM_NN>>>(
        (const uint32_t*)S, (const uint32_t*)V, out, L_, D_, L_,
        (long long)L_ * L_, (long long)L_ * D_, (long long)L_ * D_, nullptr);
}

// round 10
// speedup vs baseline: 1.1987x; 1.1716x over previous
#include <cuda_runtime.h>
#include <cstdint>

#define B_  4
#define L_  2048
#define D_  512
#define DK_ 256

// Scratch (allocation-free per harness rules)
__device__ float g_Q[B_ * L_ * DK_];
__device__ float g_K[B_ * L_ * DK_];
__device__ float g_V[B_ * L_ * D_];
__device__ float g_QE[(size_t)B_ * L_ * L_];
__device__ float g_S[(size_t)B_ * L_ * L_];

__device__ __forceinline__ uint32_t cvt_tf32(float x) {
    uint32_t r;
    asm("cvt.rna.tf32.f32 %0, %1;" : "=r"(r) : "f"(x));
    return r;
}

__device__ __forceinline__ void mma_tf32(float c[4], const uint32_t a[4], const uint32_t b[2]) {
    asm volatile(
        "mma.sync.aligned.m16n8k8.row.col.f32.tf32.tf32.f32 "
        "{%0,%1,%2,%3},{%4,%5,%6,%7},{%8,%9},{%0,%1,%2,%3};"
        : "+f"(c[0]), "+f"(c[1]), "+f"(c[2]), "+f"(c[3])
        : "r"(a[0]), "r"(a[1]), "r"(a[2]), "r"(a[3]), "r"(b[0]), "r"(b[1]));
}

__device__ __forceinline__ void ldsm4(uint32_t& r0, uint32_t& r1, uint32_t& r2, uint32_t& r3,
                                      uint32_t addr) {
    asm volatile("ldmatrix.sync.aligned.m8n8.x4.shared.b16 {%0,%1,%2,%3}, [%4];"
                 : "=r"(r0), "=r"(r1), "=r"(r2), "=r"(r3) : "r"(addr));
}

// ---------------------------------------------------------------------------
// TF32 tensor-core GEMM. Block tile 128x128, K-chunk 32, 256 threads = 8 warps
// (2x4 warp grid, warp tile 64x32). fp32 accumulate. Fragment loads via
// ldmatrix.x4 (A always; B when TRANS_B). R3-proven structure otherwise.
//   TRANS_B=false: C = A[M,K] * B[K,N]           (row-major B)
//   TRANS_B=true : C = A[M,K] * B[N,K]^T
//   SKEW=true    : C = (A*B^T + skew(QE)) * 1/16 (QK^T epilogue)
// ---------------------------------------------------------------------------
template <bool TRANS_B, bool SKEW>
__global__ __launch_bounds__(256)
void tgemm(const float* __restrict__ A, const float* __restrict__ Bm,
           float* __restrict__ C, int M, int N, int Kd,
           long long sA, long long sB, long long sC,
           const float* __restrict__ QE)
{
    // A tile: [m 0..127][k 0..31], stride 36 words
    __shared__ uint32_t As[128 * 36];
    // B tile: NT -> [n][k] stride 36; NN -> [k][n] stride 136
    __shared__ uint32_t Bs[TRANS_B ? (128 * 36) : (32 * 136)];

    const int bz = blockIdx.z;
    A  += (size_t)bz * sA;
    Bm += (size_t)bz * sB;
    C  += (size_t)bz * sC;

    const int bm = blockIdx.y * 128;
    const int bn = blockIdx.x * 128;
    const int tid  = threadIdx.x;
    const int lane = tid & 31;
    const int warp = tid >> 5;
    const int wm = warp & 1;   // 0..1  (64-row slab)
    const int wn = warp >> 1;  // 0..3  (32-col slab)

    // global-load mapping: 128x32-float tile, 4 float4 per thread
    const int arow  = tid >> 3;          // 0..31
    const int acol4 = (tid & 7) << 2;    // 0,4,..28
    // NN B tile: 32x128 floats
    const int brow  = tid >> 5;          // 0..7
    const int bcol4 = (tid & 31) << 2;   // 0..124

    // ldmatrix per-lane base addresses (bytes)
    const uint32_t asm0 = (uint32_t)__cvta_generic_to_shared(As);
    const uint32_t bsm0 = (uint32_t)__cvta_generic_to_shared(Bs);
    const int l7 = lane & 7;
    const int lA_m = (lane >> 3) & 1;    // +8 rows for matrices 1,3
    const int lA_k = lane >> 4;          // +4 k for matrices 2,3
    uint32_t aaddr[4];
#pragma unroll
    for (int mi = 0; mi < 4; mi++)
        aaddr[mi] = asm0 + ((wm * 64 + mi * 16 + l7 + 8 * lA_m) * 36 + 4 * lA_k) * 4;
    uint32_t baddr[2];
    if (TRANS_B) {
        const int lB_n = lane >> 4;          // +8 n for matrices 2,3
        const int lB_k = (lane >> 3) & 1;    // +4 k for matrices 1,3
#pragma unroll
        for (int n2 = 0; n2 < 2; n2++)
            baddr[n2] = bsm0 + ((wn * 32 + n2 * 16 + l7 + 8 * lB_n) * 36 + 4 * lB_k) * 4;
    }

    float acc[4][4][4];
#pragma unroll
    for (int i = 0; i < 4; i++)
#pragma unroll
        for (int j = 0; j < 4; j++)
#pragma unroll
            for (int e = 0; e < 4; e++) acc[i][j][e] = 0.f;

    float4 ra[4], rb[4];

    // ---- prologue global load (k0 = 0) ----
#pragma unroll
    for (int i = 0; i < 4; i++)
        ra[i] = *reinterpret_cast<const float4*>(
            A + (size_t)(bm + arow + 32 * i) * Kd + acol4);
#pragma unroll
    for (int i = 0; i < 4; i++) {
        if (TRANS_B)
            rb[i] = *reinterpret_cast<const float4*>(
                Bm + (size_t)(bn + arow + 32 * i) * Kd + acol4);
        else
            rb[i] = *reinterpret_cast<const float4*>(
                Bm + (size_t)(brow + 8 * i) * N + bn + bcol4);
    }

    for (int k0 = 0; k0 < Kd; k0 += 32) {
        // ---- store tiles to smem (cvt to tf32 bits) ----
#pragma unroll
        for (int i = 0; i < 4; i++)
            *reinterpret_cast<uint4*>(&As[(arow + 32 * i) * 36 + acol4]) =
                make_uint4(cvt_tf32(ra[i].x), cvt_tf32(ra[i].y),
                           cvt_tf32(ra[i].z), cvt_tf32(ra[i].w));
#pragma unroll
        for (int i = 0; i < 4; i++) {
            if (TRANS_B)
                *reinterpret_cast<uint4*>(&Bs[(arow + 32 * i) * 36 + acol4]) =
                    make_uint4(cvt_tf32(rb[i].x), cvt_tf32(rb[i].y),
                               cvt_tf32(rb[i].z), cvt_tf32(rb[i].w));
            else
                *reinterpret_cast<uint4*>(&Bs[(brow + 8 * i) * 136 + bcol4]) =
                    make_uint4(cvt_tf32(rb[i].x), cvt_tf32(rb[i].y),
                               cvt_tf32(rb[i].z), cvt_tf32(rb[i].w));
        }
        __syncthreads();

        // ---- prefetch next chunk into registers ----
        if (k0 + 32 < Kd) {
            const int kn = k0 + 32;
#pragma unroll
            for (int i = 0; i < 4; i++)
                ra[i] = *reinterpret_cast<const float4*>(
                    A + (size_t)(bm + arow + 32 * i) * Kd + kn + acol4);
#pragma unroll
            for (int i = 0; i < 4; i++) {
                if (TRANS_B)
                    rb[i] = *reinterpret_cast<const float4*>(
                        Bm + (size_t)(bn + arow + 32 * i) * Kd + kn + acol4);
                else
                    rb[i] = *reinterpret_cast<const float4*>(
                        Bm + (size_t)(kn + brow + 8 * i) * N + bn + bcol4);
            }
        }

        // ---- compute: 4 k8-steps, fragments via ldmatrix ----
#pragma unroll
        for (int kb = 0; kb < 4; kb++) {
            const uint32_t koff = (uint32_t)(kb * 8 * 4);  // bytes
            uint32_t af[4][4];
#pragma unroll
            for (int mi = 0; mi < 4; mi++)
                ldsm4(af[mi][0], af[mi][1], af[mi][2], af[mi][3], aaddr[mi] + koff);
            uint32_t bf[4][2];
            if (TRANS_B) {
#pragma unroll
                for (int n2 = 0; n2 < 2; n2++)
                    ldsm4(bf[2 * n2][0], bf[2 * n2][1], bf[2 * n2 + 1][0], bf[2 * n2 + 1][1],
                          baddr[n2] + koff);
            } else {
                const int kk = kb * 8;
#pragma unroll
                for (int ni = 0; ni < 4; ni++) {
                    const int n = wn * 32 + ni * 8 + (lane >> 2);
                    bf[ni][0] = Bs[(kk + (lane & 3)) * 136 + n];
                    bf[ni][1] = Bs[(kk + 4 + (lane & 3)) * 136 + n];
                }
            }
#pragma unroll
            for (int mi = 0; mi < 4; mi++)
#pragma unroll
                for (int ni = 0; ni < 4; ni++)
                    mma_tf32(acc[mi][ni], af[mi], bf[ni]);
        }
        __syncthreads();
    }

    // ---- epilogue ----
    if (!SKEW) {
#pragma unroll
        for (int mi = 0; mi < 4; mi++) {
            const int r0 = bm + wm * 64 + mi * 16 + (lane >> 2);
#pragma unroll
            for (int ni = 0; ni < 4; ni++) {
                const int c0 = bn + wn * 32 + ni * 8 + 2 * (lane & 3);
                *reinterpret_cast<float2*>(C + (size_t)r0 * N + c0) =
                    make_float2(acc[mi][ni][0], acc[mi][ni][1]);
                *reinterpret_cast<float2*>(C + (size_t)(r0 + 8) * N + c0) =
                    make_float2(acc[mi][ni][2], acc[mi][ni][3]);
            }
        }
    } else {
        // Srel[l,m] = QE[l, m-l+L-1] (m<=l); 0 (m==l+1); QE[l+1, m-l-2] (m>=l+2)
        const float scale = 0.0625f;  // 1/sqrt(256)
        const int b = blockIdx.z;
#pragma unroll
        for (int mi = 0; mi < 4; mi++) {
            const int rbase = bm + wm * 64 + mi * 16 + (lane >> 2);
#pragma unroll
            for (int ni = 0; ni < 4; ni++) {
                const int c0 = bn + wn * 32 + ni * 8 + 2 * (lane & 3);
#pragma unroll
                for (int h = 0; h < 2; h++) {
                    const int l = rbase + 8 * h;
                    const size_t row0 = (size_t)(b * L_ + l) * L_;
                    const size_t row1 = (size_t)(b * L_ + l + 1) * L_;
                    float out[2];
#pragma unroll
                    for (int e = 0; e < 2; e++) {
                        const int m = c0 + e;
                        float srel;
                        if (m <= l)          srel = QE[row0 + (m - l + L_ - 1)];
                        else if (m == l + 1) srel = 0.f;
                        else                 srel = QE[row1 + (m - l - 2)];
                        out[e] = (acc[mi][ni][2 * h + e] + srel) * scale;
                    }
                    *reinterpret_cast<float2*>(C + (size_t)l * N + c0) =
                        make_float2(out[0], out[1]);
                }
            }
        }
    }
}

// ---------------------------------------------------------------------------
// Row softmax over 2048 elements: one block per row, 256 threads x 8 elements.
// ---------------------------------------------------------------------------
__global__ void softmax2048(float* __restrict__ S)
{
    __shared__ float red[8];
    const size_t row = blockIdx.x;
    float* p = S + row * (size_t)L_;
    const int tid = threadIdx.x;

    float v[8];
    float mx = -1e30f;
#pragma unroll
    for (int i = 0; i < 8; i++) {
        v[i] = p[tid + i * 256];
        mx = fmaxf(mx, v[i]);
    }
#pragma unroll
    for (int o = 16; o > 0; o >>= 1)
        mx = fmaxf(mx, __shfl_xor_sync(0xffffffffu, mx, o));
    if ((tid & 31) == 0) red[tid >> 5] = mx;
    __syncthreads();
    mx = red[0];
#pragma unroll
    for (int w = 1; w < 8; w++) mx = fmaxf(mx, red[w]);
    __syncthreads();

    float sum = 0.f;
#pragma unroll
    for (int i = 0; i < 8; i++) {
        v[i] = __expf(v[i] - mx);
        sum += v[i];
    }
#pragma unroll
    for (int o = 16; o > 0; o >>= 1)
        sum += __shfl_xor_sync(0xffffffffu, sum, o);
    if ((tid & 31) == 0) red[tid >> 5] = sum;
    __syncthreads();
    float tot = 0.f;
#pragma unroll
    for (int w = 0; w < 8; w++) tot += red[w];

    const float inv = 1.f / tot;
#pragma unroll
    for (int i = 0; i < 8; i++) p[tid + i * 256] = v[i] * inv;
}

// ---------------------------------------------------------------------------
extern "C" void kernel_launch(void* const* d_in, const int* in_sizes, int n_in,
                              void* d_out, int out_size)
{
    const float* inQ = (const float*)d_in[0];
    const float* inK = (const float*)d_in[1];
    const float* inV = (const float*)d_in[2];
    const float* Wq  = (const float*)d_in[3];
    const float* Wk  = (const float*)d_in[4];
    const float* Wv  = (const float*)d_in[5];
    const float* E   = (const float*)d_in[6];
    float* out = (float*)d_out;

    float *Q, *K, *V, *QE, *S;
    cudaGetSymbolAddress((void**)&Q,  g_Q);
    cudaGetSymbolAddress((void**)&K,  g_K);
    cudaGetSymbolAddress((void**)&V,  g_V);
    cudaGetSymbolAddress((void**)&QE, g_QE);
    cudaGetSymbolAddress((void**)&S,  g_S);

    const int BL = B_ * L_;  // 8192

    // Projections: [8192,512] x [512,{256,256,512}] (NN)
    tgemm<false, false><<<dim3(DK_ / 128, BL / 128, 1), 256>>>(
        inQ, Wq, Q, BL, DK_, D_, 0, 0, 0, nullptr);
    tgemm<false, false><<<dim3(DK_ / 128, BL / 128, 1), 256>>>(
        inK, Wk, K, BL, DK_, D_, 0, 0, 0, nullptr);
    tgemm<false, false><<<dim3(D_ / 128, BL / 128, 1), 256>>>(
        inV, Wv, V, BL, D_, D_, 0, 0, 0, nullptr);

    // QE = Q * E^T : [8192,256] x [2048,256]^T -> [8192,2048] (NT)
    tgemm<true, false><<<dim3(L_ / 128, BL / 128, 1), 256>>>(
        Q, E, QE, BL, L_, DK_, 0, 0, 0, nullptr);

    // S = (Q K^T + skew(QE)) / 16, batched over B (NT + skew epilogue)
    tgemm<true, true><<<dim3(L_ / 128, L_ / 128, B_), 256>>>(
        Q, K, S, L_, L_, DK_,
        (long long)L_ * DK_, (long long)L_ * DK_, (long long)L_ * L_, QE);

    // softmax along rows
    softmax2048<<<BL, 256>>>(S);

    // out = P * V, batched over B: [2048,2048] x [2048,512] (NN)
    tgemm<false, false><<<dim3(D_ / 128, L_ / 128, B_), 256>>>(
        S, V, out, L_, D_, L_,
        (long long)L_ * L_, (long long)L_ * D_, (long long)L_ * D_, nullptr);
}